// round 1
// baseline (speedup 1.0000x reference)
#include <cuda_runtime.h>
#include <cstdint>

#define BDIM 8
#define NPTS 4096
#define DDIM 64
#define KNN 16
#define P1_THREADS 128
#define CHUNK 256

// Scratch (device globals -- no allocations allowed in kernel_launch).
__device__ unsigned long long g_buf[(size_t)BDIM * NPTS * CHUNK]; // 64 MB candidate ring
__device__ int g_knn[BDIM * NPTS * KNN];                          // 2 MB knn indices

// Insert (cd,cm) into sorted-ascending (dist,idx) top-16 list.
// Strict lexicographic total order (d, then index) == jnp stable argsort order.
__device__ __forceinline__ void insert16(float (&dist)[KNN], int (&idx)[KNN],
                                          float cd, int cm) {
#pragma unroll
    for (int j = 0; j < KNN; j++) {
        bool lt = (cd < dist[j]) || ((cd == dist[j]) && (cm < idx[j]));
        float od = dist[j]; int oi = idx[j];
        float nd = lt ? cd : od;
        int   ni = lt ? cm : oi;
        cd = lt ? od : cd;
        cm = lt ? oi : cm;
        dist[j] = nd; idx[j] = ni;
    }
}

// ---------------- Phase 1: fused distance + top-16 selection ----------------
// One block = 128 queries of one batch. Whole point cloud (x,y,z,||p||^2) in smem.
// Branch-free chunk scan with deferred buffered insertion.
extern "C" __global__ void __launch_bounds__(P1_THREADS)
knn_kernel(const float* __restrict__ xyz)
{
    extern __shared__ float4 cand[];   // [NPTS] = 64 KB
    int b  = blockIdx.x >> 5;                 // 32 blocks per batch
    int n0 = (blockIdx.x & 31) * P1_THREADS;
    const float* xb = xyz + (size_t)b * NPTS * 3;

    for (int m = threadIdx.x; m < NPTS; m += P1_THREADS) {
        float mx = xb[3*m], my = xb[3*m+1], mz = xb[3*m+2];
        float s = mx*mx; s = fmaf(my, my, s); s = fmaf(mz, mz, s);
        cand[m] = make_float4(mx, my, mz, s);
    }
    __syncthreads();

    int n = n0 + threadIdx.x;
    float4 q = cand[n];

    float dist[KNN]; int idx[KNN];
#pragma unroll
    for (int j = 0; j < KNN; j++) { dist[j] = 3.0e38f; idx[j] = 0x7fffffff; }

    unsigned long long* buf =
        g_buf + (size_t)(blockIdx.x * P1_THREADS + threadIdx.x) * CHUNK;

    // Seed: first 64 candidates via direct (guarded) insertion to establish threshold.
#pragma unroll 1
    for (int m = 0; m < 64; m++) {
        float4 c = cand[m];
        float t = q.x*c.x; t = fmaf(q.y, c.y, t); t = fmaf(q.z, c.z, t);
        float d = fmaf(-2.0f, t, q.w + c.w);
        if (d < dist[KNN-1]) insert16(dist, idx, d, m);
    }
    float thr = dist[KNN-1];

    // Main: 256-candidate chunks, predicated append, batch insert.
    for (int base = 64; base < NPTS; base += CHUNK) {
        int end = base + CHUNK; if (end > NPTS) end = NPTS;
        int cnt = 0;
#pragma unroll 4
        for (int m = base; m < end; m++) {
            float4 c = cand[m];
            float t = q.x*c.x; t = fmaf(q.y, c.y, t); t = fmaf(q.z, c.z, t);
            float d = fmaf(-2.0f, t, q.w + c.w);
            bool acc = d < thr;
            if (acc) {
                unsigned long long pk =
                    (unsigned long long)__float_as_uint(d) |
                    ((unsigned long long)(unsigned)m << 32);
                buf[cnt] = pk;
            }
            cnt += acc;
        }
        // warp-max trip count so insertion runs convergent
        int cm = cnt;
#pragma unroll
        for (int o = 16; o > 0; o >>= 1) {
            int t2 = __shfl_xor_sync(0xffffffffu, cm, o);
            cm = cm > t2 ? cm : t2;
        }
        for (int j = 0; j < cm; j++) {
            float cd = 3.0e38f; int ci = 0x7fffffff;   // inert sentinel for idle lanes
            if (j < cnt) {
                unsigned long long pk = buf[j];
                cd = __uint_as_float((unsigned)pk);
                ci = (int)(pk >> 32);
            }
            insert16(dist, idx, cd, ci);
        }
        thr = dist[KNN-1];
    }

    int* kp = g_knn + ((size_t)b * NPTS + n) * KNN;
#pragma unroll
    for (int k = 0; k < KNN; k++) kp[k] = idx[k];
}

// ---------------- Phase 2: MLP + transpose-add epilogue ----------------
// One thread per (b,n,k). Accumulators packed as f32x2 (Blackwell FFMA2 = 2x fp32).
extern "C" __global__ void __launch_bounds__(128)
mlp_kernel(const float* __restrict__ xyz, const float* __restrict__ x,
           const float* __restrict__ W1, const float* __restrict__ b1,
           const float* __restrict__ W2, const float* __restrict__ b2,
           float* __restrict__ out)
{
    __shared__ __align__(16) float W2s[DDIM * DDIM];
    __shared__ __align__(16) float W1s[3 * DDIM];
    __shared__ __align__(16) float b1s[DDIM];
    __shared__ __align__(16) float b2s[DDIM];

    for (int i = threadIdx.x; i < DDIM * DDIM; i += 128) W2s[i] = W2[i];
    for (int i = threadIdx.x; i < 3 * DDIM;    i += 128) W1s[i] = W1[i];
    if (threadIdx.x < DDIM) {
        b1s[threadIdx.x] = b1[threadIdx.x];
        b2s[threadIdx.x] = b2[threadIdx.x];
    }
    __syncthreads();

    int gid = blockIdx.x * 128 + threadIdx.x;     // ((b*N + n)*K + k)
    int k = gid & (KNN - 1);
    int n = (gid >> 4) & (NPTS - 1);
    int b = gid >> 16;
    int m = g_knn[gid];

    const float* xb = xyz + (size_t)b * NPTS * 3;
    float qx = xb[3*n], qy = xb[3*n+1], qz = xb[3*n+2];
    float dx = qx - xb[3*m], dy = qy - xb[3*m+1], dz = qz - xb[3*m+2];

    unsigned long long acc[DDIM / 2];
    const unsigned long long* b2p = (const unsigned long long*)b2s;
#pragma unroll
    for (int e = 0; e < DDIM / 2; e++) acc[e] = b2p[e];

#pragma unroll 4
    for (int d = 0; d < DDIM; d++) {
        float h = b1s[d];
        h = fmaf(dx, W1s[d], h);
        h = fmaf(dy, W1s[DDIM + d], h);
        h = fmaf(dz, W1s[2 * DDIM + d], h);
        h = fmaxf(h, 0.0f);
        unsigned long long h2;
        asm("mov.b64 %0, {%1, %1};" : "=l"(h2) : "r"(__float_as_int(h)));
        const ulonglong2* w = (const ulonglong2*)(W2s + (d << 6));
#pragma unroll
        for (int e = 0; e < 16; e++) {
            ulonglong2 wv = w[e];   // LDS.128 broadcast
            asm("fma.rn.f32x2 %0, %1, %2, %0;" : "+l"(acc[2*e])   : "l"(h2), "l"(wv.x));
            asm("fma.rn.f32x2 %0, %1, %2, %0;" : "+l"(acc[2*e+1]) : "l"(h2), "l"(wv.y));
        }
    }

    // out[b,k,n,:] = x[b,k,n,:] + pos_enc[b,n,k,:]
    size_t off = ((((size_t)b * KNN + k) * NPTS) + n) * DDIM;
    const ulonglong2* xr  = (const ulonglong2*)(x + off);
    ulonglong2*       orw = (ulonglong2*)(out + off);
#pragma unroll
    for (int e = 0; e < 16; e++) {
        ulonglong2 xv = xr[e];
        ulonglong2 r;
        asm("add.rn.f32x2 %0, %1, %2;" : "=l"(r.x) : "l"(acc[2*e]),   "l"(xv.x));
        asm("add.rn.f32x2 %0, %1, %2;" : "=l"(r.y) : "l"(acc[2*e+1]), "l"(xv.y));
        orw[e] = r;
    }
}

extern "C" void kernel_launch(void* const* d_in, const int* in_sizes, int n_in,
                              void* d_out, int out_size) {
    const float* xyz = (const float*)d_in[0];
    const float* x   = (const float*)d_in[1];
    const float* W1  = (const float*)d_in[2];
    const float* b1  = (const float*)d_in[3];
    const float* W2  = (const float*)d_in[4];
    const float* b2  = (const float*)d_in[5];
    float* out = (float*)d_out;

    cudaFuncSetAttribute(knn_kernel, cudaFuncAttributeMaxDynamicSharedMemorySize,
                         NPTS * (int)sizeof(float4));

    knn_kernel<<<BDIM * (NPTS / P1_THREADS), P1_THREADS, NPTS * sizeof(float4)>>>(xyz);
    mlp_kernel<<<(BDIM * NPTS * KNN) / 128, 128>>>(xyz, x, W1, b1, W2, b2, out);
}